// round 12
// baseline (speedup 1.0000x reference)
#include <cuda_runtime.h>
#include <cuda_bf16.h>
#include <math.h>
#include <stdint.h>

// Problem constants
#define BSZ 16
#define TT  500
#define EE  1024
#define VV  4000
#define LL  100
#define SS  201
#define GG  101
#define MM  (BSZ*TT)     // 8000
#define MPAD 8064        // 63*128
#define NPAD 4096        // 32*128
#define NEGF (-1e30f)
#define SELP 112
#define UNUSED_SENT 0x7fffffff

// GEMM tiling: 8 warps (2M x 4N), warp tile 64x32, BK=64 stages
#define BM 128
#define BN 128
#define BK 64
#define NST 3
#define STAGE 32768          // A 16KB + B 16KB
#define KITERS (EE/BK)       // 16
#define NTILES (NPAD/BN)     // 32

// Scratch (device globals: allocation-free per harness rules)
__device__ __nv_bfloat16 g_hsb[(size_t)MPAD * EE];   // COMPACT rows; dead rows zero
__device__ __nv_bfloat16 g_Wtb[(size_t)NPAD * EE];
__device__ int g_colidx[(size_t)BSZ * VV];
__device__ int g_us[BSZ * GG];
__device__ int g_base[BSZ + 1];
__device__ int g_live;
__device__ int g_rowsrc[MPAD];
__device__ int g_rowb[MPAD];
__device__ float2 g_part[(size_t)MM * NTILES];
__device__ float g_sel[(size_t)MM * SELP];
__device__ float g_lp[(size_t)MM * GG];
__device__ float g_ll[BSZ];

// ---------------------------------------------------------------------------
__device__ __forceinline__ uint32_t smem_u32(const void* p) {
    uint32_t a;
    asm("{ .reg .u64 t; cvta.to.shared.u64 t, %1; cvt.u32.u64 %0, t; }" : "=r"(a) : "l"(p));
    return a;
}
__device__ __forceinline__ void cp16(uint32_t dst, const void* src) {
    asm volatile("cp.async.cg.shared.global [%0], [%1], 16;" :: "r"(dst), "l"(src));
}
// 128-byte-row swizzle: (row, 16B-chunk c), c in 0..7
__device__ __forceinline__ uint32_t swz128(int row, int c) {
    return (uint32_t)(row * 128 + ((c ^ (row & 7)) << 4));
}

// ---------------------------------------------------------------------------
// Setup: block 0 = prefix + row maps; blocks 1..16 = per-batch column maps
// ---------------------------------------------------------------------------
__global__ __launch_bounds__(256)
void setup_kernel(const int* __restrict__ ilens, const int* __restrict__ ys) {
    const int tid = threadIdx.x;
    if (blockIdx.x == 0) {
        if (tid == 0) {
            int acc = 0;
            for (int b = 0; b < BSZ; b++) { g_base[b] = acc; acc += ilens[b]; }
            g_base[BSZ] = acc;
            g_live = acc;
        }
        __syncthreads();
        for (int i = tid; i < MPAD; i += 256) { g_rowsrc[i] = -1; g_rowb[i] = -1; }
        __syncthreads();
        for (int row = tid; row < MM; row += 256) {
            int b = row / TT, t = row % TT;
            if (t < ilens[b]) {
                int o = g_base[b] + t;
                g_rowsrc[o] = row;
                g_rowb[o] = b;
            }
        }
    } else {
        const int b = blockIdx.x - 1;
        for (int i = tid; i < VV; i += 256)
            g_colidx[(size_t)b * VV + i] = UNUSED_SENT;
        __syncthreads();
        int col = 0;
        if (tid < GG) {
            if (tid > 0) {
                int y = ys[b * LL + tid - 1];
                col = y < 0 ? 0 : y;
            }
            atomicMin(&g_colidx[(size_t)b * VV + col], tid);
        }
        __syncthreads();
        if (tid < GG)
            g_us[b * GG + tid] = g_colidx[(size_t)b * VV + col];
    }
}

// ---------------------------------------------------------------------------
// Conversion kernels
// ---------------------------------------------------------------------------
__global__ __launch_bounds__(256)
void conv_hs_kernel(const float* __restrict__ hs) {
    size_t i = ((size_t)blockIdx.x * 256 + threadIdx.x) * 4;
    if (i >= (size_t)MPAD * EE) return;
    int orow = (int)(i >> 10);
    int k = (int)(i & 1023);
    int src = g_rowsrc[orow];
    float4 v = make_float4(0.f, 0.f, 0.f, 0.f);
    if (src >= 0) v = *(const float4*)(hs + (size_t)src * EE + k);
    __nv_bfloat162* dst = (__nv_bfloat162*)(g_hsb + i);
    dst[0] = __nv_bfloat162(__float2bfloat16(v.x), __float2bfloat16(v.y));
    dst[1] = __nv_bfloat162(__float2bfloat16(v.z), __float2bfloat16(v.w));
}

__global__ __launch_bounds__(256)
void conv_W_kernel(const float* __restrict__ W) {
    __shared__ float t[32][33];
    int n0 = blockIdx.x * 32;
    int k0 = blockIdx.y * 32;
    int tx = threadIdx.x;
    int ty = threadIdx.y;
    if (n0 >= VV) {
#pragma unroll
        for (int j = 0; j < 32; j += 8)
            g_Wtb[(size_t)(n0 + ty + j) * EE + k0 + tx] = __float2bfloat16(0.f);
        return;
    }
#pragma unroll
    for (int j = 0; j < 32; j += 8)
        t[ty + j][tx] = W[(size_t)(k0 + ty + j) * VV + n0 + tx];
    __syncthreads();
#pragma unroll
    for (int j = 0; j < 32; j += 8)
        g_Wtb[(size_t)(n0 + ty + j) * EE + k0 + tx] = __float2bfloat16(t[tx][ty + j]);
}

// ---------------------------------------------------------------------------
// Main GEMM: 256 threads, 8 warps (2Mx4N), warp tile 64x32, BK=64 stages,
// fused LSE + selected-logit scatter. Compact rows.
// ---------------------------------------------------------------------------
__global__ __launch_bounds__(256, 2)
void gemm_lse_kernel(const float* __restrict__ bias) {
    const int by = blockIdx.y;
    const int row0 = by * BM;
    if (row0 >= g_live) return;

    extern __shared__ char dsm[];
    __shared__ float2 red[4][BM];
    __shared__ int scol[2][BM];

    const int tid = threadIdx.x;
    const int warp = tid >> 5, lane = tid & 31;
    const int wm = (warp & 1) * 64, wn = (warp >> 1) * 32;
    const int bx = blockIdx.x;
    const int col0 = bx * BN;
    const uint32_t sbase = smem_u32(dsm);

    // cp.async assignment: row = tid/2, four 16B chunks (half row each)
    const int lrow = tid >> 1;
    const int half = (tid & 1) * 4;      // chunk base 0 or 4
    uint32_t dsw[4];
#pragma unroll
    for (int j = 0; j < 4; j++) dsw[j] = swz128(lrow, half + j);
    const __nv_bfloat16* srcA = g_hsb + ((size_t)row0 + lrow) * EE + half * 8;
    const __nv_bfloat16* srcB = g_Wtb + ((size_t)col0 + lrow) * EE + half * 8;

    // Stage per-batch column maps for this tile's rows (<=2 batches).
    const int b_lo = g_rowb[row0];
    const int lastrow = (row0 + BM - 1 < g_live) ? row0 + BM - 1 : g_live - 1;
    const int b_hi = g_rowb[lastrow];
    if (tid < BM) {
        int gc = col0 + tid;
        bool okc = gc < VV;
        scol[0][tid] = okc ? g_colidx[(size_t)b_lo * VV + gc] : UNUSED_SENT;
        scol[1][tid] = (okc && b_hi >= 0) ? g_colidx[(size_t)b_hi * VV + gc] : UNUSED_SENT;
    }

    float acc[4][4][4];
#pragma unroll
    for (int mi = 0; mi < 4; mi++)
#pragma unroll
        for (int ni = 0; ni < 4; ni++)
#pragma unroll
            for (int r = 0; r < 4; r++) acc[mi][ni][r] = 0.f;

    // STAGE-RELATIVE fragment offsets; addr = (sbase + st*STAGE) + (off ^ (kk<<5))
    uint32_t aoff0[4], boff0[4];
#pragma unroll
    for (int mi = 0; mi < 4; mi++) {
        int r = wm + mi * 16 + (lane & 15);
        aoff0[mi] = swz128(r, (lane >> 4) & 1);
    }
#pragma unroll
    for (int ni = 0; ni < 4; ni++) {
        int r = wn + ni * 8 + (lane & 7);
        boff0[ni] = 16384u + swz128(r, (lane >> 3) & 1);
    }

#define LOAD_STAGE(st, kt) do { \
    uint32_t b_ = sbase + (uint32_t)(st) * STAGE; \
    const __nv_bfloat16* a_ = srcA + (kt) * BK; \
    const __nv_bfloat16* w_ = srcB + (kt) * BK; \
    cp16(b_ + dsw[0], a_); \
    cp16(b_ + dsw[1], a_ + 8); \
    cp16(b_ + dsw[2], a_ + 16); \
    cp16(b_ + dsw[3], a_ + 24); \
    cp16(b_ + 16384 + dsw[0], w_); \
    cp16(b_ + 16384 + dsw[1], w_ + 8); \
    cp16(b_ + 16384 + dsw[2], w_ + 16); \
    cp16(b_ + 16384 + dsw[3], w_ + 24); \
    asm volatile("cp.async.commit_group;" ::: "memory"); \
} while (0)

    LOAD_STAGE(0, 0);
    LOAD_STAGE(1, 1);

    int st = 0;
    for (int kt = 0; kt < KITERS; kt++) {
        if (kt < KITERS - 1)
            asm volatile("cp.async.wait_group 1;" ::: "memory");
        else
            asm volatile("cp.async.wait_group 0;" ::: "memory");
        __syncthreads();

        const uint32_t sb2 = sbase + (uint32_t)st * STAGE;
#pragma unroll
        for (int kk = 0; kk < 4; kk++) {
            const uint32_t kx = (uint32_t)kk << 5;
            uint32_t af[4][4], bf[4][2];
#pragma unroll
            for (int mi = 0; mi < 4; mi++)
                asm volatile("ldmatrix.sync.aligned.m8n8.x4.shared.b16 {%0,%1,%2,%3}, [%4];"
                             : "=r"(af[mi][0]), "=r"(af[mi][1]), "=r"(af[mi][2]), "=r"(af[mi][3])
                             : "r"(sb2 + (aoff0[mi] ^ kx)));
#pragma unroll
            for (int ni = 0; ni < 4; ni++)
                asm volatile("ldmatrix.sync.aligned.m8n8.x2.shared.b16 {%0,%1}, [%2];"
                             : "=r"(bf[ni][0]), "=r"(bf[ni][1])
                             : "r"(sb2 + (boff0[ni] ^ kx)));
#pragma unroll
            for (int mi = 0; mi < 4; mi++)
#pragma unroll
                for (int ni = 0; ni < 4; ni++)
                    asm volatile(
                        "mma.sync.aligned.m16n8k16.row.col.f32.bf16.bf16.f32 "
                        "{%0,%1,%2,%3}, {%4,%5,%6,%7}, {%8,%9}, {%0,%1,%2,%3};"
                        : "+f"(acc[mi][ni][0]), "+f"(acc[mi][ni][1]),
                          "+f"(acc[mi][ni][2]), "+f"(acc[mi][ni][3])
                        : "r"(af[mi][0]), "r"(af[mi][1]), "r"(af[mi][2]), "r"(af[mi][3]),
                          "r"(bf[ni][0]), "r"(bf[ni][1]));
        }
        if (kt + 2 < KITERS) LOAD_STAGE((st + 2 >= NST) ? st + 2 - NST : st + 2, kt + 2);
        st = (st + 1 == NST) ? 0 : st + 1;
    }
#undef LOAD_STAGE

    // Epilogue: bias add, scatter via smem map, LSE partials (max then sum)
#pragma unroll
    for (int mi = 0; mi < 4; mi++) {
        const int r1 = row0 + wm + mi * 16 + (lane >> 2);
        const int r2 = r1 + 8;
        const int b1 = g_rowb[r1];
        const int b2 = g_rowb[r2];
        const int* c1 = (b1 == b_lo) ? scol[0] : scol[1];
        const int* c2 = (b2 == b_lo) ? scol[0] : scol[1];
        float vv1[8], vv2[8];
#pragma unroll
        for (int ni = 0; ni < 4; ni++) {
            int lc = wn + ni * 8 + 2 * (lane & 3);
            int gcol = col0 + lc;
            bool ok = gcol < VV;
            float b0 = 0.f, bb = 0.f;
            if (ok) { float2 bv = *(const float2*)(bias + gcol); b0 = bv.x; bb = bv.y; }
            float a0 = acc[mi][ni][0] + b0, a1 = acc[mi][ni][1] + bb;
            float a2 = acc[mi][ni][2] + b0, a3 = acc[mi][ni][3] + bb;
            vv1[2 * ni] = ok ? a0 : NEGF; vv1[2 * ni + 1] = ok ? a1 : NEGF;
            vv2[2 * ni] = ok ? a2 : NEGF; vv2[2 * ni + 1] = ok ? a3 : NEGF;
            if (b1 >= 0) {
                int u0 = c1[lc], u1 = c1[lc + 1];
                if (u0 < GG) g_sel[(size_t)r1 * SELP + u0] = a0;
                if (u1 < GG) g_sel[(size_t)r1 * SELP + u1] = a1;
            }
            if (b2 >= 0) {
                int u0 = c2[lc], u1 = c2[lc + 1];
                if (u0 < GG) g_sel[(size_t)r2 * SELP + u0] = a2;
                if (u1 < GG) g_sel[(size_t)r2 * SELP + u1] = a3;
            }
        }
        float m1 = vv1[0], m2 = vv2[0];
#pragma unroll
        for (int j = 1; j < 8; j++) { m1 = fmaxf(m1, vv1[j]); m2 = fmaxf(m2, vv2[j]); }
        float s1 = 0.f, s2 = 0.f;
#pragma unroll
        for (int j = 0; j < 8; j++) { s1 += __expf(vv1[j] - m1); s2 += __expf(vv2[j] - m2); }

#pragma unroll
        for (int msk = 1; msk <= 2; msk <<= 1) {
            float om = __shfl_xor_sync(0xffffffffu, m1, msk);
            float os = __shfl_xor_sync(0xffffffffu, s1, msk);
            float M = fmaxf(m1, om);
            s1 = s1 * __expf(m1 - M) + os * __expf(om - M);
            m1 = M;
            om = __shfl_xor_sync(0xffffffffu, m2, msk);
            os = __shfl_xor_sync(0xffffffffu, s2, msk);
            M = fmaxf(m2, om);
            s2 = s2 * __expf(m2 - M) + os * __expf(om - M);
            m2 = M;
        }
        if ((lane & 3) == 0) {
            int rr = wm + mi * 16 + (lane >> 2);
            red[warp >> 1][rr] = make_float2(m1, s1);
            red[warp >> 1][rr + 8] = make_float2(m2, s2);
        }
    }
    __syncthreads();
    if (tid < BM) {
        float m = NEGF, s = 0.f;
#pragma unroll
        for (int j = 0; j < 4; j++) {
            float2 p = red[j][tid];
            float M = fmaxf(m, p.x);
            s = s * __expf(m - M) + p.y * __expf(p.x - M);
            m = M;
        }
        int grow = row0 + tid;
        if (grow < MM) g_part[(size_t)grow * NTILES + bx] = make_float2(m, s);
    }
}

// ---------------------------------------------------------------------------
// Combine (compact rows): lse reduce + lp[o][s] = sel[o][us[s]] - lse
// ---------------------------------------------------------------------------
__global__ __launch_bounds__(128)
void combine_kernel() {
    const int o = blockIdx.x;
    const int b = g_rowb[o];
    if (b < 0) return;

    __shared__ float s_lse;
    const int tid = threadIdx.x;
    if (tid < 32) {
        float2 p = g_part[(size_t)o * NTILES + tid];
        float m = p.x, s = p.y;
#pragma unroll
        for (int msk = 16; msk > 0; msk >>= 1) {
            float om = __shfl_xor_sync(0xffffffffu, m, msk);
            float os = __shfl_xor_sync(0xffffffffu, s, msk);
            float M = fmaxf(m, om);
            s = s * __expf(m - M) + os * __expf(om - M);
            m = M;
        }
        if (tid == 0) s_lse = m + logf(s);
    }
    __syncthreads();
    if (tid >= GG) return;
    int u = g_us[b * GG + tid];
    g_lp[(size_t)o * GG + tid] = g_sel[(size_t)o * SELP + u] - s_lse;
}

// ---------------------------------------------------------------------------
// CTC forward DP, one block per batch element (compact lp rows)
// ---------------------------------------------------------------------------
__global__ __launch_bounds__(256)
void ctc_dp_kernel(const int* __restrict__ ys, const int* __restrict__ ilens,
                   const int* __restrict__ olens) {
    extern __shared__ float sm[];
    float* lps = sm;                     // [<=TT][GG]
    float* abuf = sm + TT * GG;          // [2][256]

    const int b = blockIdx.x;
    const int tid = threadIdx.x;
    const int s = tid;
    const int ilen = ilens[b];

    const float* src = g_lp + (size_t)g_base[b] * GG;
    for (int i = tid; i < ilen * GG; i += blockDim.x) lps[i] = src[i];

    int g = 0;
    bool allow = false;
    if (s < SS && (s & 1)) {
        int l = s >> 1;
        g = 1 + l;
        int yr = ys[b * LL + l];
        int y = yr < 0 ? 0 : yr;
        int ypr = -1;
        if (l > 0) {
            int yp = ys[b * LL + l - 1];
            ypr = yp < 0 ? 0 : yp;
        }
        allow = (y != 0) && (y != ypr);
    }

    float* a0 = abuf;
    float* a1 = abuf + 256;
    a0[s] = (s == 0) ? lps[0] : ((s == 1) ? lps[1] : NEGF);
    __syncthreads();

    for (int t = 1; t < ilen; t++) {
        if (s < SS) {
            float v1 = a0[s];
            float v2 = (s >= 1) ? a0[s - 1] : NEGF;
            float v3 = (s >= 2 && allow) ? a0[s - 2] : NEGF;
            float m = fmaxf(v1, fmaxf(v2, v3));
            float sum = __expf(v1 - m) + __expf(v2 - m) + __expf(v3 - m);
            a1[s] = m + __logf(sum) + lps[t * GG + g];
        }
        __syncthreads();
        float* tmp = a0; a0 = a1; a1 = tmp;
    }

    if (tid == 0) {
        const int olen = olens[b];
        float va = a0[2 * olen];
        float vb = a0[2 * olen - 1];
        float m = fmaxf(va, vb);
        g_ll[b] = m + logf(expf(va - m) + expf(vb - m));
    }
}

__global__ void finalize_kernel(float* __restrict__ out) {
    if (threadIdx.x == 0) {
        float sum = 0.0f;
        for (int i = 0; i < BSZ; i++) sum += g_ll[i];
        out[0] = -sum / (float)BSZ;
    }
}

// ---------------------------------------------------------------------------
extern "C" void kernel_launch(void* const* d_in, const int* in_sizes, int n_in,
                              void* d_out, int out_size) {
    const float* hs    = (const float*)d_in[0];
    const float* W     = (const float*)d_in[1];
    const float* bias  = (const float*)d_in[2];
    const int*   ys    = (const int*)d_in[3];
    const int*   ilens = (const int*)d_in[4];
    const int*   olens = (const int*)d_in[5];
    float* out = (float*)d_out;

    setup_kernel<<<1 + BSZ, 256>>>(ilens, ys);                   // launch 1
    conv_hs_kernel<<<(MPAD * EE) / 1024, 256>>>(hs);             // launch 2
    conv_W_kernel<<<dim3(NPAD / 32, EE / 32), dim3(32, 8)>>>(W); // launch 3

    const int gemm_smem = NST * STAGE;   // 96 KB
    cudaFuncSetAttribute(gemm_lse_kernel,
                         cudaFuncAttributeMaxDynamicSharedMemorySize, gemm_smem);
    dim3 ggrid(NPAD / BN, MPAD / BM);    // 32 x 63
    gemm_lse_kernel<<<ggrid, 256, gemm_smem>>>(bias);            // launch 4 (profiled)

    combine_kernel<<<MM, 128>>>();                               // launch 5

    const int dp_smem = TT * GG * sizeof(float) + 2 * 256 * sizeof(float);
    cudaFuncSetAttribute(ctc_dp_kernel,
                         cudaFuncAttributeMaxDynamicSharedMemorySize, dp_smem);
    ctc_dp_kernel<<<BSZ, 256, dp_smem>>>(ys, ilens, olens);      // launch 6

    finalize_kernel<<<1, 32>>>(out);                             // launch 7
}